// round 1
// baseline (speedup 1.0000x reference)
#include <cuda_runtime.h>
#include <math.h>

// Problem constants (fixed by setup_inputs)
#define NCAP 50000
#define MCAP 10000
#define ECAP 600000
#define H 128
#define H2 256
#define OUTD 64

// ---------------- scratch (device globals; no allocation allowed) ----------
__device__ float    g_xe [MCAP*H];     // refined hyperedge features
__device__ float    g_h  [NCAP*H];     // node features (reused across stages)
__device__ float    g_me [MCAP*H];     // hyperedge mean accum
__device__ float    g_mv [NCAP*H];     // node mean accum / (h+mv) input
__device__ float    g_q  [NCAP*H];
__device__ float    g_k  [MCAP*H];
__device__ float    g_v  [MCAP*H];
__device__ float    g_s  [ECAP];       // scores -> exp values
__device__ unsigned g_smax[NCAP];      // mapped float max
__device__ float    g_den [NCAP];
__device__ float    g_h2 [NCAP*H];     // attention output accum
__device__ unsigned g_agg[MCAP*H];     // mapped float min
__device__ float    g_z  [MCAP*H2];    // concat buffer
__device__ float    g_z2 [MCAP*H];     // ef output
__device__ float    g_tmp[MCAP*H];     // MLP intermediates
__device__ int      g_cnt_e[MCAP];
__device__ int      g_cnt_v[NCAP];
__device__ float    g_cs1 [H2], g_cs1b[H2];
__device__ float    g_cs2 [H],  g_cs2b[H];
__device__ float    g_sc1 [H2], g_sh1 [H2];
__device__ float    g_sc2 [H],  g_sh2 [H];

// ---------------- monotone float<->unsigned mapping (for atomic max/min) ----
__device__ __forceinline__ unsigned fmap(float f) {
    unsigned u = __float_as_uint(f);
    return (u & 0x80000000u) ? ~u : (u | 0x80000000u);
}
__device__ __forceinline__ float funmap(unsigned u) {
    return __uint_as_float((u & 0x80000000u) ? (u & 0x7FFFFFFFu) : ~u);
}

__device__ __forceinline__ float lrelu(float v, float sl) {
    return v > 0.f ? v : sl * v;
}

// ---------------- init (re-zero accumulators each replay) -------------------
__global__ void init_all() {
    int i = blockIdx.x * blockDim.x + threadIdx.x;
    int stride = gridDim.x * blockDim.x;
    for (int t = i; t < NCAP*H; t += stride) { g_mv[t] = 0.f; g_h2[t] = 0.f; }
    for (int t = i; t < MCAP*H; t += stride) { g_me[t] = 0.f; g_agg[t] = 0xFFFFFFFFu; }
    for (int t = i; t < NCAP;   t += stride) { g_den[t] = 0.f; g_cnt_v[t] = 0; g_smax[t] = 0u; }
    for (int t = i; t < MCAP;   t += stride) { g_cnt_e[t] = 0; }
    for (int t = i; t < H2;     t += stride) { g_cs1[t] = 0.f; g_cs1b[t] = 0.f; }
    for (int t = i; t < H;      t += stride) { g_cs2[t] = 0.f; g_cs2b[t] = 0.f; }
}

// ---------------- SIMT fp32 GEMM: C[rows,NCOL] = act(A[rows,K] @ W + bias) --
template<int K, int NCOL, bool ACT>
__global__ void __launch_bounds__(256)
gemm_kernel(const float* __restrict__ A, const float* __restrict__ W,
            const float* __restrict__ bias, float* __restrict__ C, int rows)
{
    constexpr int BM = 64, KC = 16, TN = NCOL / 16;
    __shared__ float As[KC][BM + 1];
    __shared__ float Ws[KC][NCOL + 1];
    int tid = threadIdx.x;
    int tr = tid >> 4, tc = tid & 15;
    int row0 = blockIdx.x * BM;
    float acc[4][TN];
#pragma unroll
    for (int r = 0; r < 4; r++)
#pragma unroll
        for (int c = 0; c < TN; c++) acc[r][c] = 0.f;

    for (int k0 = 0; k0 < K; k0 += KC) {
#pragma unroll
        for (int i = tid; i < BM * KC; i += 256) {
            int r = i >> 4, kk = i & 15;
            int row = row0 + r;
            As[kk][r] = (row < rows) ? A[(size_t)row * K + k0 + kk] : 0.f;
        }
#pragma unroll
        for (int i = tid; i < KC * NCOL; i += 256) {
            int kk = i / NCOL, c = i % NCOL;
            Ws[kk][c] = W[(size_t)(k0 + kk) * NCOL + c];
        }
        __syncthreads();
#pragma unroll
        for (int kk = 0; kk < KC; kk++) {
            float a[4], w[TN];
#pragma unroll
            for (int r = 0; r < 4; r++) a[r] = As[kk][tr * 4 + r];
#pragma unroll
            for (int c = 0; c < TN; c++) w[c] = Ws[kk][tc + 16 * c];
#pragma unroll
            for (int r = 0; r < 4; r++)
#pragma unroll
                for (int c = 0; c < TN; c++)
                    acc[r][c] = fmaf(a[r], w[c], acc[r][c]);
        }
        __syncthreads();
    }
#pragma unroll
    for (int r = 0; r < 4; r++) {
        int row = row0 + tr * 4 + r;
        if (row < rows) {
#pragma unroll
            for (int c = 0; c < TN; c++) {
                int col = tc + 16 * c;
                float v = acc[r][c] + (bias ? bias[col] : 0.f);
                if (ACT) v = lrelu(v, 0.01f);
                C[(size_t)row * NCOL + col] = v;
            }
        }
    }
}

// ---------------- edge kernels ----------------------------------------------
__global__ void count_kernel(const int* __restrict__ nidx, const int* __restrict__ hidx, int E) {
    int i = blockIdx.x * blockDim.x + threadIdx.x;
    if (i >= E) return;
    atomicAdd(&g_cnt_e[hidx[i]], 1);
    atomicAdd(&g_cnt_v[nidx[i]], 1);
}

// warp per edge: dst[didx[e]] += src[sidx[e]]
__global__ void scatter_add_kernel(const float* __restrict__ src,
                                   const int* __restrict__ sidx,
                                   const int* __restrict__ didx,
                                   float* __restrict__ dst, int E)
{
    int w = (blockIdx.x * blockDim.x + threadIdx.x) >> 5;
    if (w >= E) return;
    int lane = threadIdx.x & 31;
    int sr = sidx[w], ds = didx[w];
    float4 val = ((const float4*)(src + (size_t)sr * H))[lane];
    float* d = dst + (size_t)ds * H + lane * 4;
    atomicAdd(d + 0, val.x); atomicAdd(d + 1, val.y);
    atomicAdd(d + 2, val.z); atomicAdd(d + 3, val.w);
}

__global__ void me_norm_kernel(int M) {
    int i = blockIdx.x * blockDim.x + threadIdx.x;
    if (i >= M * H) return;
    float inv = 1.0f / fmaxf((float)g_cnt_e[i >> 7], 1.0f);
    g_me[i] *= inv;
}

__global__ void hin_kernel(int N) {
    int i = blockIdx.x * blockDim.x + threadIdx.x;
    if (i >= N * H) return;
    float inv = 1.0f / fmaxf((float)g_cnt_v[i >> 7], 1.0f);
    g_mv[i] = g_h[i] + g_mv[i] * inv;
}

__global__ void att_score_kernel(const float* __restrict__ q, const float* __restrict__ k,
                                 const int* __restrict__ nidx, const int* __restrict__ hidx,
                                 int E)
{
    int w = (blockIdx.x * blockDim.x + threadIdx.x) >> 5;
    if (w >= E) return;
    int lane = threadIdx.x & 31;
    int n = nidx[w], m = hidx[w];
    float4 a = ((const float4*)(q + (size_t)n * H))[lane];
    float4 b = ((const float4*)(k + (size_t)m * H))[lane];
    float d = a.x * b.x + a.y * b.y + a.z * b.z + a.w * b.w;
#pragma unroll
    for (int o = 16; o; o >>= 1) d += __shfl_xor_sync(0xFFFFFFFFu, d, o);
    if (lane == 0) {
        d *= 0.08838834764831845f;   // 1/sqrt(128)
        d = lrelu(d, 0.2f);
        g_s[w] = d;
        atomicMax(&g_smax[n], fmap(d));
    }
}

__global__ void att_exp_kernel(const int* __restrict__ nidx, int E) {
    int i = blockIdx.x * blockDim.x + threadIdx.x;
    if (i >= E) return;
    int n = nidx[i];
    float mx = funmap(g_smax[n]);
    float e = expf(g_s[i] - mx);
    g_s[i] = e;
    atomicAdd(&g_den[n], e);
}

// warp per edge: h2[nidx[e]] += s[e] * v[hidx[e]]
__global__ void att_scatter_kernel(const int* __restrict__ nidx, const int* __restrict__ hidx, int E) {
    int w = (blockIdx.x * blockDim.x + threadIdx.x) >> 5;
    if (w >= E) return;
    int lane = threadIdx.x & 31;
    int n = nidx[w], m = hidx[w];
    float e = g_s[w];
    float4 val = ((const float4*)(g_v + (size_t)m * H))[lane];
    float* d = g_h2 + (size_t)n * H + lane * 4;
    atomicAdd(d + 0, e * val.x); atomicAdd(d + 1, e * val.y);
    atomicAdd(d + 2, e * val.z); atomicAdd(d + 3, e * val.w);
}

__global__ void h2_norm_kernel(int N) {
    int i = blockIdx.x * blockDim.x + threadIdx.x;
    if (i >= N * H) return;
    float inv = 1.0f / fmaxf(g_den[i >> 7], 1e-16f);
    g_h2[i] *= inv;
}

// warp per edge: agg[hidx[e]] = min(agg, h2[nidx[e]])
__global__ void scatter_min_kernel(const int* __restrict__ nidx, const int* __restrict__ hidx, int E) {
    int w = (blockIdx.x * blockDim.x + threadIdx.x) >> 5;
    if (w >= E) return;
    int lane = threadIdx.x & 31;
    int n = nidx[w], m = hidx[w];
    float4 val = ((const float4*)(g_h2 + (size_t)n * H))[lane];
    unsigned* d = g_agg + (size_t)m * H + lane * 4;
    atomicMin(d + 0, fmap(val.x)); atomicMin(d + 1, fmap(val.y));
    atomicMin(d + 2, fmap(val.z)); atomicMin(d + 3, fmap(val.w));
}

__global__ void build_z_kernel(int M) {
    int i = blockIdx.x * blockDim.x + threadIdx.x;
    if (i >= M * H2) return;
    int m = i / H2, c = i % H2;
    float v;
    if (c < H) v = (g_cnt_e[m] > 0) ? funmap(g_agg[m * H + c]) : 0.f;
    else       v = g_xe[m * H + (c - H)];
    g_z[i] = v;
}

// ---------------- GraphNorm -------------------------------------------------
__global__ void gn_stats_kernel(const float* __restrict__ X, int C, int rows,
                                float* __restrict__ cs, float* __restrict__ cs2) {
    int c = threadIdx.x;                 // blockDim.x == C
    int r0 = blockIdx.x * 64;
    int r1 = min(r0 + 64, rows);
    float s = 0.f, s2 = 0.f;
    for (int r = r0; r < r1; r++) {
        float v = X[(size_t)r * C + c];
        s += v; s2 = fmaf(v, v, s2);
    }
    atomicAdd(&cs[c], s);
    atomicAdd(&cs2[c], s2);
}

__global__ void gn_coef_kernel(int C, int rows,
                               const float* __restrict__ w, const float* __restrict__ a,
                               const float* __restrict__ cs, const float* __restrict__ cs2,
                               float* __restrict__ sc, float* __restrict__ sh) {
    int c = blockIdx.x * blockDim.x + threadIdx.x;
    if (c >= C) return;
    float inv = 1.0f / (float)rows;
    float mu = cs[c] * inv;
    float m2 = cs2[c] * inv;
    float av = a[c];
    float var = m2 - mu * mu * av * (2.f - av);   // mean((x - a*mu)^2)
    sc[c] = w[c] * rsqrtf(var + 1e-5f);
    sh[c] = av * mu;
}

__global__ void gn_apply_kernel(float* __restrict__ X, int C, int total,
                                const float* __restrict__ sc, const float* __restrict__ sh,
                                const float* __restrict__ b, int act) {
    int i = blockIdx.x * blockDim.x + threadIdx.x;
    if (i >= total) return;
    int c = i % C;
    float v = sc[c] * (X[i] - sh[c]) + b[c];
    if (act) v = lrelu(v, 0.01f);
    X[i] = v;
}

// ---------------- launch ----------------------------------------------------
static inline int cdiv(int a, int b) { return (a + b - 1) / b; }

extern "C" void kernel_launch(void* const* d_in, const int* in_sizes, int n_in,
                              void* d_out, int out_size)
{
    const float* x      = (const float*)d_in[0];
    const float* x_e    = (const float*)d_in[2];
    const int*   nidx   = (const int*)  d_in[3];
    const int*   hidx   = (const int*)  d_in[4];
    const float* her_W1 = (const float*)d_in[5];
    const float* her_b1 = (const float*)d_in[6];
    const float* her_W2 = (const float*)d_in[7];
    const float* her_b2 = (const float*)d_in[8];
    const float* sr_W1  = (const float*)d_in[9];
    const float* sr_b1  = (const float*)d_in[10];
    const float* sr_W2  = (const float*)d_in[11];
    const float* sr_b2  = (const float*)d_in[12];
    const float* att_Wq = (const float*)d_in[13];
    const float* att_Wk = (const float*)d_in[14];
    const float* att_Wv = (const float*)d_in[15];
    const float* ef_W   = (const float*)d_in[16];
    const float* ef_b   = (const float*)d_in[17];
    const float* gn1_w  = (const float*)d_in[18];
    const float* gn1_b  = (const float*)d_in[19];
    const float* gn1_a  = (const float*)d_in[20];
    const float* gn2_w  = (const float*)d_in[21];
    const float* gn2_b  = (const float*)d_in[22];
    const float* gn2_a  = (const float*)d_in[23];
    const float* cls_W1 = (const float*)d_in[24];
    const float* cls_b1 = (const float*)d_in[25];
    const float* cls_W2 = (const float*)d_in[26];
    const float* cls_b2 = (const float*)d_in[27];
    float* out = (float*)d_out;

    const int N = in_sizes[0] / H;
    const int M = in_sizes[2] / H;
    const int E = in_sizes[3];

    // scratch pointers (device-global symbols)
    float *p_xe, *p_h, *p_me, *p_mv, *p_q, *p_k, *p_v, *p_z, *p_z2, *p_tmp;
    float *p_cs1, *p_cs1b, *p_cs2, *p_cs2b, *p_sc1, *p_sh1, *p_sc2, *p_sh2;
    cudaGetSymbolAddress((void**)&p_xe,  g_xe);
    cudaGetSymbolAddress((void**)&p_h,   g_h);
    cudaGetSymbolAddress((void**)&p_me,  g_me);
    cudaGetSymbolAddress((void**)&p_mv,  g_mv);
    cudaGetSymbolAddress((void**)&p_q,   g_q);
    cudaGetSymbolAddress((void**)&p_k,   g_k);
    cudaGetSymbolAddress((void**)&p_v,   g_v);
    cudaGetSymbolAddress((void**)&p_z,   g_z);
    cudaGetSymbolAddress((void**)&p_z2,  g_z2);
    cudaGetSymbolAddress((void**)&p_tmp, g_tmp);
    cudaGetSymbolAddress((void**)&p_cs1, g_cs1);
    cudaGetSymbolAddress((void**)&p_cs1b,g_cs1b);
    cudaGetSymbolAddress((void**)&p_cs2, g_cs2);
    cudaGetSymbolAddress((void**)&p_cs2b,g_cs2b);
    cudaGetSymbolAddress((void**)&p_sc1, g_sc1);
    cudaGetSymbolAddress((void**)&p_sh1, g_sh1);
    cudaGetSymbolAddress((void**)&p_sc2, g_sc2);
    cudaGetSymbolAddress((void**)&p_sh2, g_sh2);

    const int TB = 256;
    const int eb  = cdiv(E, TB);          // thread-per-edge grids
    const int ewb = cdiv(E * 32, TB);     // warp-per-edge grids

    // 0. reset accumulators
    init_all<<<1024, TB>>>();

    // 1. hyperedge MLP: xe = act(x_e@W1+b1)@W2+b2
    gemm_kernel<H, H, true ><<<cdiv(M, 64), TB>>>(x_e,  her_W1, her_b1, p_tmp, M);
    gemm_kernel<H, H, false><<<cdiv(M, 64), TB>>>(p_tmp,her_W2, her_b2, p_xe,  M);

    // 2. node MLP layer 1: h = act(x@W1+b1)
    gemm_kernel<H, H, true ><<<cdiv(N, 64), TB>>>(x, sr_W1, sr_b1, p_h, N);

    // 3. degree counts
    count_kernel<<<eb, TB>>>(nidx, hidx, E);

    // 4. node -> hyperedge mean
    scatter_add_kernel<<<ewb, TB>>>(p_h, nidx, hidx, p_me, E);
    me_norm_kernel<<<cdiv(M * H, TB), TB>>>(M);

    // 5. hyperedge -> node mean, then h = act((h+mv)@W2+b2)
    scatter_add_kernel<<<ewb, TB>>>(p_me, hidx, nidx, p_mv, E);
    hin_kernel<<<cdiv(N * H, TB), TB>>>(N);
    gemm_kernel<H, H, true ><<<cdiv(N, 64), TB>>>(p_mv, sr_W2, sr_b2, p_h, N);

    // 6. attention projections (no bias)
    gemm_kernel<H, H, false><<<cdiv(N, 64), TB>>>(p_h,  att_Wq, nullptr, p_q, N);
    gemm_kernel<H, H, false><<<cdiv(M, 64), TB>>>(p_xe, att_Wk, nullptr, p_k, M);
    gemm_kernel<H, H, false><<<cdiv(M, 64), TB>>>(p_xe, att_Wv, nullptr, p_v, M);

    // 7. segment softmax attention + aggregation
    att_score_kernel<<<ewb, TB>>>(p_q, p_k, nidx, hidx, E);
    att_exp_kernel<<<eb, TB>>>(nidx, E);
    att_scatter_kernel<<<ewb, TB>>>(nidx, hidx, E);
    h2_norm_kernel<<<cdiv(N * H, TB), TB>>>(N);

    // 8. min aggregation into hyperedges
    scatter_min_kernel<<<ewb, TB>>>(nidx, hidx, E);

    // 9. concat + GraphNorm1
    build_z_kernel<<<cdiv(M * H2, TB), TB>>>(M);
    gn_stats_kernel<<<cdiv(M, 64), H2>>>(p_z, H2, M, p_cs1, p_cs1b);
    gn_coef_kernel<<<1, H2>>>(H2, M, gn1_w, gn1_a, p_cs1, p_cs1b, p_sc1, p_sh1);
    gn_apply_kernel<<<cdiv(M * H2, TB), TB>>>(p_z, H2, M * H2, p_sc1, p_sh1, gn1_b, 0);

    // 10. edge fusion linear + act, GraphNorm2 + act
    gemm_kernel<H2, H, true><<<cdiv(M, 64), TB>>>(p_z, ef_W, ef_b, p_z2, M);
    gn_stats_kernel<<<cdiv(M, 64), H>>>(p_z2, H, M, p_cs2, p_cs2b);
    gn_coef_kernel<<<1, H>>>(H, M, gn2_w, gn2_a, p_cs2, p_cs2b, p_sc2, p_sh2);
    gn_apply_kernel<<<cdiv(M * H, TB), TB>>>(p_z2, H, M * H, p_sc2, p_sh2, gn2_b, 1);

    // 11. classifier
    gemm_kernel<H, H,    true ><<<cdiv(M, 64), TB>>>(p_z2,  cls_W1, cls_b1, p_tmp, M);
    gemm_kernel<H, OUTD, false><<<cdiv(M, 64), TB>>>(p_tmp, cls_W2, cls_b2, out,   M);
}

// round 2
// speedup vs baseline: 1.3588x; 1.3588x over previous
#include <cuda_runtime.h>
#include <math.h>

#define NCAP 50000
#define MCAP 10000
#define ECAP 600000
#define H 128
#define H2 256
#define OUTD 64

// ---------------- scratch (device globals; no allocation allowed) ----------
__device__ float    g_xe [MCAP*H];
__device__ float    g_h  [NCAP*H];
__device__ float    g_me [MCAP*H];
__device__ float    g_mv [NCAP*H];
__device__ float    g_q  [NCAP*H];
__device__ float    g_k  [MCAP*H];
__device__ float    g_v  [MCAP*H];
__device__ float    g_s  [ECAP];
__device__ unsigned g_smax[NCAP];
__device__ float    g_den [NCAP];
__device__ float    g_h2 [NCAP*H];
__device__ unsigned g_agg[MCAP*H];
__device__ float    g_z  [MCAP*H2];
__device__ float    g_z2 [MCAP*H];
__device__ float    g_tmp[MCAP*H];
__device__ int      g_cnt_e[MCAP];
__device__ int      g_cnt_v[NCAP];
__device__ float    g_cs1 [H2], g_cs1b[H2];
__device__ float    g_cs2 [H],  g_cs2b[H];
__device__ float    g_sc1 [H2], g_sh1 [H2];
__device__ float    g_sc2 [H],  g_sh2 [H];

// ---------------- helpers ---------------------------------------------------
__device__ __forceinline__ unsigned fmap(float f) {
    unsigned u = __float_as_uint(f);
    return (u & 0x80000000u) ? ~u : (u | 0x80000000u);
}
__device__ __forceinline__ float funmap(unsigned u) {
    return __uint_as_float((u & 0x80000000u) ? (u & 0x7FFFFFFFu) : ~u);
}
__device__ __forceinline__ float lrelu(float v, float sl) {
    return v > 0.f ? v : sl * v;
}
// sm_90+ vectorized global float reduction (one instruction, 16B)
__device__ __forceinline__ void red_add_v4(float* addr, float4 v) {
    asm volatile("red.global.add.v4.f32 [%0], {%1,%2,%3,%4};"
                 :: "l"(addr), "f"(v.x), "f"(v.y), "f"(v.z), "f"(v.w) : "memory");
}

// ---------------- init ------------------------------------------------------
__global__ void init_all() {
    int i = blockIdx.x * blockDim.x + threadIdx.x;
    int stride = gridDim.x * blockDim.x;
    for (int t = i; t < NCAP*H; t += stride) { g_mv[t] = 0.f; g_h2[t] = 0.f; }
    for (int t = i; t < MCAP*H; t += stride) { g_me[t] = 0.f; g_agg[t] = 0xFFFFFFFFu; }
    for (int t = i; t < NCAP;   t += stride) { g_den[t] = 0.f; g_cnt_v[t] = 0; g_smax[t] = 0u; }
    for (int t = i; t < MCAP;   t += stride) { g_cnt_e[t] = 0; }
    for (int t = i; t < H2;     t += stride) { g_cs1[t] = 0.f; g_cs1b[t] = 0.f; }
    for (int t = i; t < H;      t += stride) { g_cs2[t] = 0.f; g_cs2b[t] = 0.f; }
}

// ---------------- GEMM: C[rows,NCOL] = act(A[rows,K] @ W + bias) ------------
// 128-row block tile, full-NCOL column tile, 256 threads, 8 x TN thread tile.
template<int K, int NCOL, bool ACT>
__global__ void __launch_bounds__(256)
gemm_kernel(const float* __restrict__ A, const float* __restrict__ W,
            const float* __restrict__ bias, float* __restrict__ C, int rows)
{
    constexpr int BM = 128, KC = 16, TN = NCOL / 16;   // TN = 8 or 4
    __shared__ float As[KC][BM];
    __shared__ float Ws[KC][NCOL];
    const int tid = threadIdx.x;
    const int tr = tid >> 4;        // 0..15 -> rows tr*8..tr*8+7
    const int tc = tid & 15;        // 0..15 -> cols tc*TN..tc*TN+TN-1
    const int row0 = blockIdx.x * BM;
    const bool full = (row0 + BM) <= rows;

    float acc[8][TN];
#pragma unroll
    for (int r = 0; r < 8; r++)
#pragma unroll
        for (int c = 0; c < TN; c++) acc[r][c] = 0.f;

    for (int k0 = 0; k0 < K; k0 += KC) {
        // load A tile (transpose to As[kk][row])
        if (full) {
#pragma unroll
            for (int t = 0; t < 2; t++) {
                int g = tid + t * 256;             // over 512 float4s
                int row = g >> 2, c4 = (g & 3) * 4;
                float4 f = *(const float4*)(A + (size_t)(row0 + row) * K + k0 + c4);
                As[c4 + 0][row] = f.x; As[c4 + 1][row] = f.y;
                As[c4 + 2][row] = f.z; As[c4 + 3][row] = f.w;
            }
        } else {
#pragma unroll
            for (int t = 0; t < 2; t++) {
                int g = tid + t * 256;
                int row = g >> 2, c4 = (g & 3) * 4;
                float4 f = make_float4(0.f, 0.f, 0.f, 0.f);
                if (row0 + row < rows)
                    f = *(const float4*)(A + (size_t)(row0 + row) * K + k0 + c4);
                As[c4 + 0][row] = f.x; As[c4 + 1][row] = f.y;
                As[c4 + 2][row] = f.z; As[c4 + 3][row] = f.w;
            }
        }
        // load W tile
#pragma unroll
        for (int g = tid; g < KC * NCOL / 4; g += 256) {
            int c4 = g % (NCOL / 4), kk = g / (NCOL / 4);
            *(float4*)&Ws[kk][c4 * 4] =
                *(const float4*)(W + (size_t)(k0 + kk) * NCOL + c4 * 4);
        }
        __syncthreads();
#pragma unroll
        for (int kk = 0; kk < KC; kk++) {
            float a[8], w[TN];
            *(float4*)&a[0] = *(const float4*)&As[kk][tr * 8];
            *(float4*)&a[4] = *(const float4*)&As[kk][tr * 8 + 4];
#pragma unroll
            for (int j = 0; j < TN / 4; j++)
                *(float4*)&w[j * 4] = *(const float4*)&Ws[kk][tc * TN + j * 4];
#pragma unroll
            for (int r = 0; r < 8; r++)
#pragma unroll
                for (int c = 0; c < TN; c++)
                    acc[r][c] = fmaf(a[r], w[c], acc[r][c]);
        }
        __syncthreads();
    }

    float bb[TN];
#pragma unroll
    for (int c = 0; c < TN; c++) bb[c] = bias ? bias[tc * TN + c] : 0.f;
#pragma unroll
    for (int r = 0; r < 8; r++) {
        int row = row0 + tr * 8 + r;
        if (row < rows) {
            float o[TN];
#pragma unroll
            for (int c = 0; c < TN; c++) {
                float v = acc[r][c] + bb[c];
                o[c] = ACT ? lrelu(v, 0.01f) : v;
            }
#pragma unroll
            for (int j = 0; j < TN / 4; j++)
                *(float4*)(C + (size_t)row * NCOL + tc * TN + j * 4) = *(float4*)&o[j * 4];
        }
    }
}

// ---------------- edge kernels ----------------------------------------------
__global__ void count_kernel(const int* __restrict__ nidx, const int* __restrict__ hidx, int E) {
    int i = blockIdx.x * blockDim.x + threadIdx.x;
    if (i >= E) return;
    atomicAdd(&g_cnt_e[hidx[i]], 1);
    atomicAdd(&g_cnt_v[nidx[i]], 1);
}

// warp per edge: dst[didx[e]] += src[sidx[e]] * (scale ? 1/max(scale[sidx[e]],1) : 1)
template<bool SCALED>
__global__ void scatter_add_kernel(const float* __restrict__ src,
                                   const int* __restrict__ sidx,
                                   const int* __restrict__ didx,
                                   const int* __restrict__ scnt,
                                   float* __restrict__ dst, int E)
{
    int w = (blockIdx.x * blockDim.x + threadIdx.x) >> 5;
    if (w >= E) return;
    int lane = threadIdx.x & 31;
    int sr = sidx[w], ds = didx[w];
    float4 val = ((const float4*)(src + (size_t)sr * H))[lane];
    if (SCALED) {
        float inv = 1.0f / fmaxf((float)scnt[sr], 1.0f);
        val.x *= inv; val.y *= inv; val.z *= inv; val.w *= inv;
    }
    red_add_v4(dst + (size_t)ds * H + lane * 4, val);
}

__global__ void hin_kernel(int N) {
    int i = blockIdx.x * blockDim.x + threadIdx.x;
    if (i >= N * H) return;
    float inv = 1.0f / fmaxf((float)g_cnt_v[i >> 7], 1.0f);
    g_mv[i] = g_h[i] + g_mv[i] * inv;
}

__global__ void att_score_kernel(const float* __restrict__ q, const float* __restrict__ k,
                                 const int* __restrict__ nidx, const int* __restrict__ hidx,
                                 int E)
{
    int w = (blockIdx.x * blockDim.x + threadIdx.x) >> 5;
    if (w >= E) return;
    int lane = threadIdx.x & 31;
    int n = nidx[w], m = hidx[w];
    float4 a = ((const float4*)(q + (size_t)n * H))[lane];
    float4 b = ((const float4*)(k + (size_t)m * H))[lane];
    float d = a.x * b.x + a.y * b.y + a.z * b.z + a.w * b.w;
#pragma unroll
    for (int o = 16; o; o >>= 1) d += __shfl_xor_sync(0xFFFFFFFFu, d, o);
    if (lane == 0) {
        d *= 0.08838834764831845f;   // 1/sqrt(128)
        d = lrelu(d, 0.2f);
        g_s[w] = d;
        atomicMax(&g_smax[n], fmap(d));
    }
}

__global__ void att_exp_kernel(const int* __restrict__ nidx, int E) {
    int i = blockIdx.x * blockDim.x + threadIdx.x;
    if (i >= E) return;
    int n = nidx[i];
    float mx = funmap(g_smax[n]);
    float e = expf(g_s[i] - mx);
    g_s[i] = e;
    atomicAdd(&g_den[n], e);
}

__global__ void att_scatter_kernel(const int* __restrict__ nidx, const int* __restrict__ hidx, int E) {
    int w = (blockIdx.x * blockDim.x + threadIdx.x) >> 5;
    if (w >= E) return;
    int lane = threadIdx.x & 31;
    int n = nidx[w], m = hidx[w];
    float e = g_s[w];
    float4 val = ((const float4*)(g_v + (size_t)m * H))[lane];
    val.x *= e; val.y *= e; val.z *= e; val.w *= e;
    red_add_v4(g_h2 + (size_t)n * H + lane * 4, val);
}

// warp per edge: agg[hidx[e]] = min(agg, h2[nidx[e]] / den[nidx[e]])
__global__ void scatter_min_kernel(const int* __restrict__ nidx, const int* __restrict__ hidx, int E) {
    int w = (blockIdx.x * blockDim.x + threadIdx.x) >> 5;
    if (w >= E) return;
    int lane = threadIdx.x & 31;
    int n = nidx[w], m = hidx[w];
    float inv = 1.0f / fmaxf(g_den[n], 1e-16f);
    float4 val = ((const float4*)(g_h2 + (size_t)n * H))[lane];
    unsigned* d = g_agg + (size_t)m * H + lane * 4;
    atomicMin(d + 0, fmap(val.x * inv)); atomicMin(d + 1, fmap(val.y * inv));
    atomicMin(d + 2, fmap(val.z * inv)); atomicMin(d + 3, fmap(val.w * inv));
}

__global__ void build_z_kernel(int M) {
    int i = blockIdx.x * blockDim.x + threadIdx.x;
    if (i >= M * H2) return;
    int m = i / H2, c = i % H2;
    float v;
    if (c < H) v = (g_cnt_e[m] > 0) ? funmap(g_agg[m * H + c]) : 0.f;
    else       v = g_xe[m * H + (c - H)];
    g_z[i] = v;
}

// ---------------- GraphNorm -------------------------------------------------
__global__ void gn_stats_kernel(const float* __restrict__ X, int C, int rows,
                                float* __restrict__ cs, float* __restrict__ cs2) {
    int c = threadIdx.x;
    int r0 = blockIdx.x * 64;
    int r1 = min(r0 + 64, rows);
    float s = 0.f, s2 = 0.f;
    for (int r = r0; r < r1; r++) {
        float v = X[(size_t)r * C + c];
        s += v; s2 = fmaf(v, v, s2);
    }
    atomicAdd(&cs[c], s);
    atomicAdd(&cs2[c], s2);
}

__global__ void gn_coef_kernel(int C, int rows,
                               const float* __restrict__ w, const float* __restrict__ a,
                               const float* __restrict__ cs, const float* __restrict__ cs2,
                               float* __restrict__ sc, float* __restrict__ sh) {
    int c = blockIdx.x * blockDim.x + threadIdx.x;
    if (c >= C) return;
    float inv = 1.0f / (float)rows;
    float mu = cs[c] * inv;
    float m2 = cs2[c] * inv;
    float av = a[c];
    float var = m2 - mu * mu * av * (2.f - av);
    sc[c] = w[c] * rsqrtf(var + 1e-5f);
    sh[c] = av * mu;
}

__global__ void gn_apply_kernel(float* __restrict__ X, int C, int total,
                                const float* __restrict__ sc, const float* __restrict__ sh,
                                const float* __restrict__ b, int act) {
    int i = blockIdx.x * blockDim.x + threadIdx.x;
    if (i >= total) return;
    int c = i % C;
    float v = sc[c] * (X[i] - sh[c]) + b[c];
    if (act) v = lrelu(v, 0.01f);
    X[i] = v;
}

// ---------------- launch ----------------------------------------------------
static inline int cdiv(int a, int b) { return (a + b - 1) / b; }

extern "C" void kernel_launch(void* const* d_in, const int* in_sizes, int n_in,
                              void* d_out, int out_size)
{
    const float* x      = (const float*)d_in[0];
    const float* x_e    = (const float*)d_in[2];
    const int*   nidx   = (const int*)  d_in[3];
    const int*   hidx   = (const int*)  d_in[4];
    const float* her_W1 = (const float*)d_in[5];
    const float* her_b1 = (const float*)d_in[6];
    const float* her_W2 = (const float*)d_in[7];
    const float* her_b2 = (const float*)d_in[8];
    const float* sr_W1  = (const float*)d_in[9];
    const float* sr_b1  = (const float*)d_in[10];
    const float* sr_W2  = (const float*)d_in[11];
    const float* sr_b2  = (const float*)d_in[12];
    const float* att_Wq = (const float*)d_in[13];
    const float* att_Wk = (const float*)d_in[14];
    const float* att_Wv = (const float*)d_in[15];
    const float* ef_W   = (const float*)d_in[16];
    const float* ef_b   = (const float*)d_in[17];
    const float* gn1_w  = (const float*)d_in[18];
    const float* gn1_b  = (const float*)d_in[19];
    const float* gn1_a  = (const float*)d_in[20];
    const float* gn2_w  = (const float*)d_in[21];
    const float* gn2_b  = (const float*)d_in[22];
    const float* gn2_a  = (const float*)d_in[23];
    const float* cls_W1 = (const float*)d_in[24];
    const float* cls_b1 = (const float*)d_in[25];
    const float* cls_W2 = (const float*)d_in[26];
    const float* cls_b2 = (const float*)d_in[27];
    float* out = (float*)d_out;

    const int N = in_sizes[0] / H;
    const int M = in_sizes[2] / H;
    const int E = in_sizes[3];

    float *p_xe, *p_h, *p_me, *p_mv, *p_q, *p_k, *p_v, *p_z, *p_z2, *p_tmp;
    float *p_cs1, *p_cs1b, *p_cs2, *p_cs2b, *p_sc1, *p_sh1, *p_sc2, *p_sh2;
    int *p_cnt_e;
    cudaGetSymbolAddress((void**)&p_xe,  g_xe);
    cudaGetSymbolAddress((void**)&p_h,   g_h);
    cudaGetSymbolAddress((void**)&p_me,  g_me);
    cudaGetSymbolAddress((void**)&p_mv,  g_mv);
    cudaGetSymbolAddress((void**)&p_q,   g_q);
    cudaGetSymbolAddress((void**)&p_k,   g_k);
    cudaGetSymbolAddress((void**)&p_v,   g_v);
    cudaGetSymbolAddress((void**)&p_z,   g_z);
    cudaGetSymbolAddress((void**)&p_z2,  g_z2);
    cudaGetSymbolAddress((void**)&p_tmp, g_tmp);
    cudaGetSymbolAddress((void**)&p_cs1, g_cs1);
    cudaGetSymbolAddress((void**)&p_cs1b,g_cs1b);
    cudaGetSymbolAddress((void**)&p_cs2, g_cs2);
    cudaGetSymbolAddress((void**)&p_cs2b,g_cs2b);
    cudaGetSymbolAddress((void**)&p_sc1, g_sc1);
    cudaGetSymbolAddress((void**)&p_sh1, g_sh1);
    cudaGetSymbolAddress((void**)&p_sc2, g_sc2);
    cudaGetSymbolAddress((void**)&p_sh2, g_sh2);
    cudaGetSymbolAddress((void**)&p_cnt_e, g_cnt_e);

    const int TB = 256;
    const int eb  = cdiv(E, TB);
    const int ewb = cdiv(E * 32, TB);

    init_all<<<1024, TB>>>();

    // hyperedge MLP
    gemm_kernel<H, H, true ><<<cdiv(M, 128), TB>>>(x_e,  her_W1, her_b1, p_tmp, M);
    gemm_kernel<H, H, false><<<cdiv(M, 128), TB>>>(p_tmp,her_W2, her_b2, p_xe,  M);

    // node MLP layer 1
    gemm_kernel<H, H, true ><<<cdiv(N, 128), TB>>>(x, sr_W1, sr_b1, p_h, N);

    // degree counts
    count_kernel<<<eb, TB>>>(nidx, hidx, E);

    // node -> hyperedge sum (mean applied on read in next scatter)
    scatter_add_kernel<false><<<ewb, TB>>>(p_h, nidx, hidx, nullptr, p_me, E);
    // hyperedge -> node mean (scale each source row by 1/cnt_e)
    scatter_add_kernel<true ><<<ewb, TB>>>(p_me, hidx, nidx, p_cnt_e, p_mv, E);
    hin_kernel<<<cdiv(N * H, TB), TB>>>(N);
    gemm_kernel<H, H, true ><<<cdiv(N, 128), TB>>>(p_mv, sr_W2, sr_b2, p_h, N);

    // attention projections
    gemm_kernel<H, H, false><<<cdiv(N, 128), TB>>>(p_h,  att_Wq, nullptr, p_q, N);
    gemm_kernel<H, H, false><<<cdiv(M, 128), TB>>>(p_xe, att_Wk, nullptr, p_k, M);
    gemm_kernel<H, H, false><<<cdiv(M, 128), TB>>>(p_xe, att_Wv, nullptr, p_v, M);

    // segment softmax attention
    att_score_kernel<<<ewb, TB>>>(p_q, p_k, nidx, hidx, E);
    att_exp_kernel<<<eb, TB>>>(nidx, E);
    att_scatter_kernel<<<ewb, TB>>>(nidx, hidx, E);

    // min aggregation (den normalization fused into read)
    scatter_min_kernel<<<ewb, TB>>>(nidx, hidx, E);

    // concat + GraphNorm1
    build_z_kernel<<<cdiv(M * H2, TB), TB>>>(M);
    gn_stats_kernel<<<cdiv(M, 64), H2>>>(p_z, H2, M, p_cs1, p_cs1b);
    gn_coef_kernel<<<1, H2>>>(H2, M, gn1_w, gn1_a, p_cs1, p_cs1b, p_sc1, p_sh1);
    gn_apply_kernel<<<cdiv(M * H2, TB), TB>>>(p_z, H2, M * H2, p_sc1, p_sh1, gn1_b, 0);

    // edge fusion + GraphNorm2
    gemm_kernel<H2, H, true><<<cdiv(M, 128), TB>>>(p_z, ef_W, ef_b, p_z2, M);
    gn_stats_kernel<<<cdiv(M, 64), H>>>(p_z2, H, M, p_cs2, p_cs2b);
    gn_coef_kernel<<<1, H>>>(H, M, gn2_w, gn2_a, p_cs2, p_cs2b, p_sc2, p_sh2);
    gn_apply_kernel<<<cdiv(M * H, TB), TB>>>(p_z2, H, M * H, p_sc2, p_sh2, gn2_b, 1);

    // classifier
    gemm_kernel<H, H,    true ><<<cdiv(M, 128), TB>>>(p_z2,  cls_W1, cls_b1, p_tmp, M);
    gemm_kernel<H, OUTD, false><<<cdiv(M, 128), TB>>>(p_tmp, cls_W2, cls_b2, out,   M);
}